// round 6
// baseline (speedup 1.0000x reference)
#include <cuda_runtime.h>

#define N_NODES 20000
#define DEG     16
#define C1      128
#define C2      256
#define NGR     16
#define NPG     1250   // nodes per graph (20000/16)

// ---------------- scratch (device globals; no allocation allowed) -------------
__device__ float g_x1[N_NODES * C1];        // conv1 output       [N,128]
__device__ float g_P [N_NODES * C2];        // x1 @ c2_W1a + b1   [N,256]  (L2-resident, 20MB)
__device__ float g_x2[N_NODES * C2];        // conv2 output       [N,256]
__device__ float g_part[NGR * 16 * C2];     // partial graph-max pool

// ---------------- f32x2 packed-FMA helpers (Blackwell, PTX-only) --------------
__device__ __forceinline__ unsigned long long pack2(float lo, float hi) {
    unsigned long long r;
    asm("mov.b64 %0, {%1, %2};" : "=l"(r) : "f"(lo), "f"(hi));
    return r;
}
__device__ __forceinline__ void ffma2(unsigned long long &acc,
                                      unsigned long long a,
                                      unsigned long long b) {
    asm("fma.rn.f32x2 %0, %1, %2, %0;" : "+l"(acc) : "l"(a), "l"(b));
}
__device__ __forceinline__ float2 unpack2(unsigned long long v) {
    float lo, hi;
    asm("mov.b64 {%0, %1}, %2;" : "=f"(lo), "=f"(hi) : "l"(v));
    return make_float2(lo, hi);
}

// =============================================================================
// Kernel 1: conv1 fused.  Per dst node d: 16 edges, msg[16,6] -> relu(@W1+b1)
// -> h1[16,128] (smem, transposed [k][j]) -> @W2 -> max over 16 -> x1[d,128]+b2
// 128 threads = 128 output channels. W2 (64KB) staged in smem once per block.
// =============================================================================
#define K1_SW2   0
#define K1_SH    (C1*C1)                 // 16384
#define K1_SMSG  (K1_SH + C1*20)         // + 2560
#define K1_SMEMF (K1_SMSG + DEG*8)       // + 128

__global__ __launch_bounds__(128, 2)
void k_conv1(const float* __restrict__ pos, const int* __restrict__ esrc,
             const float* __restrict__ W1, const float* __restrict__ b1,
             const float* __restrict__ W2, const float* __restrict__ b2)
{
    extern __shared__ float sm[];
    float* sW2  = sm + K1_SW2;    // [128][128]  (k-major, c contiguous)
    float* sH   = sm + K1_SH;     // [128][20]   h1 transposed: row k, 16 edges + pad
    float* sMsg = sm + K1_SMSG;   // [16][8]

    const int c = threadIdx.x;    // output channel

    for (int i = c; i < C1*C1; i += 128) sW2[i] = W2[i];

    float w1r[6];
    #pragma unroll
    for (int i = 0; i < 6; i++) w1r[i] = W1[i*C1 + c];
    const float b1c = b1[c];
    const float b2c = b2[c];
    __syncthreads();

    for (int d = blockIdx.x; d < N_NODES; d += gridDim.x) {
        // ---- phase A: build msg[16][6] (16 threads) ----
        if (c < DEG) {
            const int j = c;
            const int s = esrc[d*DEG + j];
            const float psx = pos[s*3+0], psy = pos[s*3+1], psz = pos[s*3+2];
            const float pdx = pos[d*3+0], pdy = pos[d*3+1], pdz = pos[d*3+2];
            float* m = sMsg + j*8;
            m[0]=psx; m[1]=psy; m[2]=psz;
            m[3]=psx-pdx; m[4]=psy-pdy; m[5]=psz-pdz;
        }
        __syncthreads();

        // ---- phase B: h1[j][c] = relu(msg@W1 + b1), store transposed ----
        #pragma unroll
        for (int j = 0; j < DEG; j++) {
            const float* m = sMsg + j*8;
            float h = b1c;
            #pragma unroll
            for (int i = 0; i < 6; i++) h = fmaf(m[i], w1r[i], h);
            sH[c*20 + j] = fmaxf(h, 0.0f);
        }
        __syncthreads();

        // ---- phase C: out[c] = max_j (h1[j,:] @ W2[:,c]) + b2[c] ----
        unsigned long long a0=0ull,a1=0ull,a2=0ull,a3=0ull,a4=0ull,a5=0ull,a6=0ull,a7=0ull;
        #pragma unroll 4
        for (int k = 0; k < C1; k++) {
            const float w = sW2[k*C1 + c];
            const unsigned long long ww = pack2(w, w);
            const ulonglong2* hp = reinterpret_cast<const ulonglong2*>(sH + k*20);
            const ulonglong2 h0 = hp[0];
            const ulonglong2 h1v = hp[1];
            const ulonglong2 h2 = hp[2];
            const ulonglong2 h3 = hp[3];
            ffma2(a0, h0.x, ww);  ffma2(a1, h0.y, ww);
            ffma2(a2, h1v.x, ww); ffma2(a3, h1v.y, ww);
            ffma2(a4, h2.x, ww);  ffma2(a5, h2.y, ww);
            ffma2(a6, h3.x, ww);  ffma2(a7, h3.y, ww);
        }
        float m = -3.4e38f;
        {
            float2 f;
            f = unpack2(a0); m = fmaxf(m, fmaxf(f.x, f.y));
            f = unpack2(a1); m = fmaxf(m, fmaxf(f.x, f.y));
            f = unpack2(a2); m = fmaxf(m, fmaxf(f.x, f.y));
            f = unpack2(a3); m = fmaxf(m, fmaxf(f.x, f.y));
            f = unpack2(a4); m = fmaxf(m, fmaxf(f.x, f.y));
            f = unpack2(a5); m = fmaxf(m, fmaxf(f.x, f.y));
            f = unpack2(a6); m = fmaxf(m, fmaxf(f.x, f.y));
            f = unpack2(a7); m = fmaxf(m, fmaxf(f.x, f.y));
        }
        g_x1[d*C1 + c] = m + b2c;
        // no trailing sync needed: next phase A touches only sMsg (phase C reads sH/sW2),
        // and phase B is gated by the post-A barrier.
    }
}

// =============================================================================
// Kernel 2: P[n,o] = b1[o] + x1[n,:] @ c2_W1[0:128,o].  W1a (128KB) in smem.
// Processes 4 nodes at a time with f32x2 pairs across nodes.
// =============================================================================
#define K2_SW    0
#define K2_SX4   (C1*C2)            // 32768
#define K2_SMEMF (K2_SX4 + C1*4)

__global__ __launch_bounds__(256, 1)
void k_proj(const float* __restrict__ W1a, const float* __restrict__ b1)
{
    extern __shared__ float sm[];
    float* sW  = sm + K2_SW;    // [128][256]
    float* sX4 = sm + K2_SX4;   // [128][4]  (k-major, 4 nodes contiguous)

    const int o = threadIdx.x;
    for (int i = o; i < C1*C2; i += 256) sW[i] = W1a[i];
    const float bo = b1[o];
    __syncthreads();

    for (int d = blockIdx.x*4; d < N_NODES; d += gridDim.x*4) {
        if (o < C1) {
            #pragma unroll
            for (int nn = 0; nn < 4; nn++)
                sX4[o*4 + nn] = g_x1[(d+nn)*C1 + o];
        }
        __syncthreads();

        unsigned long long acc01 = pack2(bo, bo);
        unsigned long long acc23 = pack2(bo, bo);
        #pragma unroll 4
        for (int k = 0; k < C1; k++) {
            const float w = sW[k*C2 + o];
            const unsigned long long ww = pack2(w, w);
            const ulonglong2 xv = *reinterpret_cast<const ulonglong2*>(sX4 + k*4);
            ffma2(acc01, xv.x, ww);
            ffma2(acc23, xv.y, ww);
        }
        const float2 f01 = unpack2(acc01);
        const float2 f23 = unpack2(acc23);
        g_P[(d+0)*C2 + o] = f01.x;
        g_P[(d+1)*C2 + o] = f01.y;
        g_P[(d+2)*C2 + o] = f23.x;
        g_P[(d+3)*C2 + o] = f23.y;
        __syncthreads();
    }
}

// =============================================================================
// Kernel 3: conv2 fused, two 128-channel passes (W2 half = 128KB smem).
// pass = blockIdx.x & 1.  Per node: gather P[src] (+ rel@W1b, relu) -> h1[16,256]
// in smem (transposed), then [16,256]@[256,128] with f32x2, max over 16 edges.
// 256 threads: c = tid&127 (channel), jh = tid>>7 (edge half, 8 edges each).
// =============================================================================
#define K3_SW2   0
#define K3_SH    (C2*C1)                 // 32768
#define K3_SRED  (K3_SH + C2*20)         // + 5120
#define K3_SREL  (K3_SRED + 256)
#define K3_SSRC  (K3_SREL + DEG*4)
#define K3_SMEMF (K3_SSRC + DEG)

__global__ __launch_bounds__(256, 1)
void k_conv2(const float* __restrict__ pos, const int* __restrict__ esrc,
             const float* __restrict__ W1full, const float* __restrict__ W2,
             const float* __restrict__ b2)
{
    extern __shared__ float sm[];
    float* sW2  = sm + K3_SW2;   // [256][128]  this pass's half of W2
    float* sH   = sm + K3_SH;    // [256][20]   h1 transposed
    float* sRed = sm + K3_SRED;  // [256]
    float* sRel = sm + K3_SREL;  // [16][4]
    int*   sSrc = reinterpret_cast<int*>(sm + K3_SSRC);

    const int tid  = threadIdx.x;
    const int pass = blockIdx.x & 1;

    for (int i = tid; i < C2*C1; i += 256) {
        const int k  = i >> 7;
        const int cc = i & 127;
        sW2[i] = W2[k*C2 + pass*C1 + cc];
    }
    // W1b rows (rel part of conv2 layer-1), b1 already folded into g_P
    const float w1b0 = W1full[(C1+0)*C2 + tid];
    const float w1b1 = W1full[(C1+1)*C2 + tid];
    const float w1b2 = W1full[(C1+2)*C2 + tid];

    const int c  = tid & 127;
    const int jh = tid >> 7;
    float b2c = 0.0f;
    if (tid < 128) b2c = b2[pass*C1 + tid];
    __syncthreads();

    for (int d = (blockIdx.x >> 1); d < N_NODES; d += (gridDim.x >> 1)) {
        // ---- phase A: src ids + rel vectors ----
        if (tid < DEG) {
            const int j = tid;
            const int s = esrc[d*DEG + j];
            sSrc[j] = s;
            sRel[j*4+0] = pos[s*3+0] - pos[d*3+0];
            sRel[j*4+1] = pos[s*3+1] - pos[d*3+1];
            sRel[j*4+2] = pos[s*3+2] - pos[d*3+2];
        }
        __syncthreads();

        // ---- phase B: h1[j][o=tid] = relu(P[src_j][o] + rel_j @ W1b[:,o]) ----
        {
            int sj[DEG];
            #pragma unroll
            for (int j = 0; j < DEG; j++) sj[j] = sSrc[j];
            float v[DEG];
            #pragma unroll
            for (int j = 0; j < DEG; j++) v[j] = g_P[sj[j]*C2 + tid];
            #pragma unroll
            for (int j = 0; j < DEG; j++) {
                float t = v[j];
                t = fmaf(sRel[j*4+0], w1b0, t);
                t = fmaf(sRel[j*4+1], w1b1, t);
                t = fmaf(sRel[j*4+2], w1b2, t);
                sH[tid*20 + j] = fmaxf(t, 0.0f);
            }
        }
        __syncthreads();

        // ---- phase C: GEMM + max over this thread's 8 edges ----
        unsigned long long a0=0ull, a1=0ull, a2=0ull, a3=0ull;
        const float* hbase = sH + jh*8;
        #pragma unroll 4
        for (int k = 0; k < C2; k++) {
            const float w = sW2[k*C1 + c];
            const unsigned long long ww = pack2(w, w);
            const ulonglong2* hp = reinterpret_cast<const ulonglong2*>(hbase + k*20);
            const ulonglong2 h0 = hp[0];
            const ulonglong2 h1v = hp[1];
            ffma2(a0, h0.x, ww);
            ffma2(a1, h0.y, ww);
            ffma2(a2, h1v.x, ww);
            ffma2(a3, h1v.y, ww);
        }
        float m = -3.4e38f;
        {
            float2 f;
            f = unpack2(a0); m = fmaxf(m, fmaxf(f.x, f.y));
            f = unpack2(a1); m = fmaxf(m, fmaxf(f.x, f.y));
            f = unpack2(a2); m = fmaxf(m, fmaxf(f.x, f.y));
            f = unpack2(a3); m = fmaxf(m, fmaxf(f.x, f.y));
        }
        sRed[tid] = m;
        __syncthreads();
        if (tid < 128) {
            g_x2[d*C2 + pass*C1 + tid] = fmaxf(sRed[tid], sRed[128 + tid]) + b2c;
        }
        // no trailing sync needed: next phase A writes sSrc/sRel only; the post-A
        // barrier gates phase B's sH overwrite behind everyone's phase C.
        __syncthreads();
    }
}

// =============================================================================
// Kernel 4a: partial global-max pool. grid = 16 graphs * 16 chunks.
// =============================================================================
__global__ void k_pool_partial()
{
    const int g  = blockIdx.x >> 4;
    const int ch = blockIdx.x & 15;
    const int cidx  = threadIdx.x;
    const int s = (ch     * NPG) >> 4;
    const int e = ((ch+1) * NPG) >> 4;
    float m = -3.4e38f;
    #pragma unroll 4
    for (int n = s; n < e; n++)
        m = fmaxf(m, g_x2[(g*NPG + n)*C2 + cidx]);
    g_part[(g*16 + ch)*C2 + cidx] = m;
}

// =============================================================================
// Kernel 4b: final pool + FC head. 16 blocks (one per graph), 256 threads.
// =============================================================================
__global__ __launch_bounds__(256)
void k_head(const float* __restrict__ fc1W, const float* __restrict__ fc1b,
            const float* __restrict__ fc2W, const float* __restrict__ fc2b,
            const float* __restrict__ labW, const float* __restrict__ labb,
            const float* __restrict__ boxW, const float* __restrict__ boxb,
            float* __restrict__ out)
{
    __shared__ float sp[C2];
    __shared__ float sy1[C2];
    __shared__ float sy2[C1];
    const int g = blockIdx.x;
    const int t = threadIdx.x;

    float m = -3.4e38f;
    #pragma unroll
    for (int ch = 0; ch < 16; ch++)
        m = fmaxf(m, g_part[(g*16 + ch)*C2 + t]);
    sp[t] = m;
    __syncthreads();

    float a = fc1b[t];
    #pragma unroll 8
    for (int k = 0; k < C2; k++) a = fmaf(sp[k], fc1W[k*C2 + t], a);
    sy1[t] = fmaxf(a, 0.0f);
    __syncthreads();

    if (t < C1) {
        float b = fc2b[t];
        #pragma unroll 8
        for (int k = 0; k < C2; k++) b = fmaf(sy1[k], fc2W[k*C1 + t], b);
        sy2[t] = fmaxf(b, 0.0f);
    }
    __syncthreads();

    if (t < 10) {
        float a2 = labb[t];
        #pragma unroll 8
        for (int k = 0; k < C1; k++) a2 = fmaf(sy2[k], labW[k*10 + t], a2);
        out[g*10 + t] = a2;                       // labels [16,10]
    } else if (t >= 32 && t < 38) {
        const int bt = t - 32;
        float a2 = boxb[bt];
        #pragma unroll 8
        for (int k = 0; k < C1; k++) a2 = fmaf(sy2[k], boxW[k*6 + bt], a2);
        out[NGR*10 + g*6 + bt] = a2;              // bbox [16,6] after labels
    }
}

// =============================================================================
extern "C" void kernel_launch(void* const* d_in, const int* in_sizes, int n_in,
                              void* d_out, int out_size)
{
    const float* pos  = (const float*)d_in[0];
    const int*   esrc = (const int*)  d_in[1];
    // d_in[2] edge_dst = repeat(arange(N),16), d_in[3] batch = n/1250 (structural)
    const float* c1W1 = (const float*)d_in[4];
    const float* c1b1 = (const float*)d_in[5];
    const float* c1W2 = (const float*)d_in[6];
    const float* c1b2 = (const float*)d_in[7];
    const float* c2W1 = (const float*)d_in[8];
    const float* c2b1 = (const float*)d_in[9];
    const float* c2W2 = (const float*)d_in[10];
    const float* c2b2 = (const float*)d_in[11];
    const float* fc1W = (const float*)d_in[12];
    const float* fc1b = (const float*)d_in[13];
    const float* fc2W = (const float*)d_in[14];
    const float* fc2b = (const float*)d_in[15];
    const float* labW = (const float*)d_in[16];
    const float* labb = (const float*)d_in[17];
    const float* boxW = (const float*)d_in[18];
    const float* boxb = (const float*)d_in[19];
    float* out = (float*)d_out;

    cudaFuncSetAttribute(k_conv1, cudaFuncAttributeMaxDynamicSharedMemorySize, K1_SMEMF*4);
    cudaFuncSetAttribute(k_proj,  cudaFuncAttributeMaxDynamicSharedMemorySize, K2_SMEMF*4);
    cudaFuncSetAttribute(k_conv2, cudaFuncAttributeMaxDynamicSharedMemorySize, K3_SMEMF*4);

    k_conv1<<<296, 128, K1_SMEMF*4>>>(pos, esrc, c1W1, c1b1, c1W2, c1b2);
    k_proj <<<148, 256, K2_SMEMF*4>>>(c2W1, c2b1);
    k_conv2<<<296, 256, K3_SMEMF*4>>>(pos, esrc, c2W1, c2W2, c2b2);
    k_pool_partial<<<NGR*16, 256>>>();
    k_head<<<NGR, 256>>>(fc1W, fc1b, fc2W, fc2b, labW, labb, boxW, boxb, out);
}

// round 10
// speedup vs baseline: 1.4529x; 1.4529x over previous
#include <cuda_runtime.h>

#define N_NODES 20000
#define DEG     16
#define C1      128
#define C2      256
#define NGR     16
#define NPG     1250   // nodes per graph (20000/16)
#define PCH     80     // pool chunks per graph

// ---------------- scratch (device globals; no allocation allowed) -------------
__device__ float g_x1[N_NODES * C1];        // conv1 output       [N,128]
__device__ float g_P [N_NODES * C2];        // x1 @ c2_W1a + b1   [N,256]  (L2-resident, 20MB)
__device__ float g_x2[N_NODES * C2];        // conv2 output       [N,256]
__device__ float g_part[NGR * PCH * C2];    // partial graph-max pool

// ---------------- f32x2 packed-FMA helpers (Blackwell, PTX-only) --------------
__device__ __forceinline__ unsigned long long pack2(float lo, float hi) {
    unsigned long long r;
    asm("mov.b64 %0, {%1, %2};" : "=l"(r) : "f"(lo), "f"(hi));
    return r;
}
__device__ __forceinline__ void ffma2(unsigned long long &acc,
                                      unsigned long long a,
                                      unsigned long long b) {
    asm("fma.rn.f32x2 %0, %1, %2, %0;" : "+l"(acc) : "l"(a), "l"(b));
}
__device__ __forceinline__ float2 unpack2(unsigned long long v) {
    float lo, hi;
    asm("mov.b64 {%0, %1}, %2;" : "=f"(lo), "=f"(hi) : "l"(v));
    return make_float2(lo, hi);
}

// =============================================================================
// Kernel 1: conv1 fused, depth-2 pipelined edge gather.
// Per node: msg[16,6] -> relu(@W1+b1) -> h1[16,128] (smem, transposed) -> @W2
// -> max over 16 -> x1[d,128]+b2.  128 threads = 128 channels, 2 blocks/SM.
// =============================================================================
#define K1_SW2   0
#define K1_SH    (C1*C1)                 // 16384
#define K1_SMSG  (K1_SH + C1*20)         // + 2560
#define K1_SMEMF (K1_SMSG + DEG*8)       // + 128

__global__ __launch_bounds__(128, 2)
void k_conv1(const float* __restrict__ pos, const int* __restrict__ esrc,
             const float* __restrict__ W1, const float* __restrict__ b1,
             const float* __restrict__ W2, const float* __restrict__ b2)
{
    extern __shared__ float sm[];
    float* sW2  = sm + K1_SW2;    // [128][128]  (k-major, c contiguous)
    float* sH   = sm + K1_SH;     // [128][20]   h1 transposed
    float* sMsg = sm + K1_SMSG;   // [16][8]

    const int c = threadIdx.x;
    const int S = gridDim.x;
    const int base = blockIdx.x;

    for (int i = c; i < C1*C1; i += 128) sW2[i] = W2[i];

    float w1r[6];
    #pragma unroll
    for (int i = 0; i < 6; i++) w1r[i] = W1[i*C1 + c];
    const float b1c = b1[c];
    const float b2c = b2[c];

    // ---- prologue: msg(base) direct, prefetch esrc(base+S) ----
    if (c < DEG) {
        const int s = esrc[base*DEG + c];
        const float pdx = pos[base*3+0], pdy = pos[base*3+1], pdz = pos[base*3+2];
        const float psx = pos[s*3+0], psy = pos[s*3+1], psz = pos[s*3+2];
        float* m = sMsg + c*8;
        m[0]=psx; m[1]=psy; m[2]=psz;
        m[3]=psx-pdx; m[4]=psy-pdy; m[5]=psz-pdz;
    }
    int rSrcA = 0;
    if (c < DEG && base + S < N_NODES) rSrcA = esrc[(base+S)*DEG + c];
    __syncthreads();

    for (int d = base; d < N_NODES; d += S) {
        // ---- phase B: h1[j][c] = relu(msg@W1 + b1) ----
        #pragma unroll
        for (int j = 0; j < DEG; j++) {
            const float* m = sMsg + j*8;
            float h = b1c;
            #pragma unroll
            for (int i = 0; i < 6; i++) h = fmaf(m[i], w1r[i], h);
            sH[c*20 + j] = fmaxf(h, 0.0f);
        }
        // prefetch esrc for d+2S (depth-2)
        int rSrcB = 0;
        const int d2 = d + 2*S;
        if (c < DEG && d2 < N_NODES) rSrcB = esrc[d2*DEG + c];
        __syncthreads();   // (1) sH ready, sMsg free

        // issue pos loads for next node (esrc already arrived); hidden under C
        const int dn = d + S;
        const bool hn = (dn < N_NODES);
        float psx=0.f, psy=0.f, psz=0.f, pdx=0.f, pdy=0.f, pdz=0.f;
        if (c < DEG && hn) {
            psx = pos[rSrcA*3+0]; psy = pos[rSrcA*3+1]; psz = pos[rSrcA*3+2];
            pdx = pos[dn*3+0];    pdy = pos[dn*3+1];    pdz = pos[dn*3+2];
        }

        // ---- phase C: out[c] = max_j (h1[j,:] @ W2[:,c]) + b2[c] ----
        unsigned long long a0=0ull,a1=0ull,a2=0ull,a3=0ull,a4=0ull,a5=0ull,a6=0ull,a7=0ull;
        #pragma unroll 4
        for (int k = 0; k < C1; k++) {
            const float w = sW2[k*C1 + c];
            const unsigned long long ww = pack2(w, w);
            const ulonglong2* hp = reinterpret_cast<const ulonglong2*>(sH + k*20);
            const ulonglong2 h0 = hp[0];
            const ulonglong2 h1v = hp[1];
            const ulonglong2 h2 = hp[2];
            const ulonglong2 h3 = hp[3];
            ffma2(a0, h0.x, ww);  ffma2(a1, h0.y, ww);
            ffma2(a2, h1v.x, ww); ffma2(a3, h1v.y, ww);
            ffma2(a4, h2.x, ww);  ffma2(a5, h2.y, ww);
            ffma2(a6, h3.x, ww);  ffma2(a7, h3.y, ww);
        }
        float m = -3.4e38f;
        {
            float2 f;
            f = unpack2(a0); m = fmaxf(m, fmaxf(f.x, f.y));
            f = unpack2(a1); m = fmaxf(m, fmaxf(f.x, f.y));
            f = unpack2(a2); m = fmaxf(m, fmaxf(f.x, f.y));
            f = unpack2(a3); m = fmaxf(m, fmaxf(f.x, f.y));
            f = unpack2(a4); m = fmaxf(m, fmaxf(f.x, f.y));
            f = unpack2(a5); m = fmaxf(m, fmaxf(f.x, f.y));
            f = unpack2(a6); m = fmaxf(m, fmaxf(f.x, f.y));
            f = unpack2(a7); m = fmaxf(m, fmaxf(f.x, f.y));
        }
        g_x1[d*C1 + c] = m + b2c;

        // store msg(d+S) from prefetched pos
        if (c < DEG && hn) {
            float* mm = sMsg + c*8;
            mm[0]=psx; mm[1]=psy; mm[2]=psz;
            mm[3]=psx-pdx; mm[4]=psy-pdy; mm[5]=psz-pdz;
        }
        rSrcA = rSrcB;
        __syncthreads();   // (2) sMsg ready for next B
    }
}

// =============================================================================
// Kernel 2: P[n,o] = b1[o] + x1[n,:] @ c2_W1[0:128,o].  W1a (128KB) in smem.
// 8 nodes per iteration; f32x2 pairs across nodes -> 8 issue / 8 fma per k.
// =============================================================================
#define K2_SW    0
#define K2_SX    (C1*C2)            // 32768
#define K2_SMEMF (K2_SX + C1*8)

__global__ __launch_bounds__(256, 1)
void k_proj(const float* __restrict__ W1a, const float* __restrict__ b1)
{
    extern __shared__ float sm[];
    float* sW = sm + K2_SW;     // [128][256]
    float* sX = sm + K2_SX;     // [128][8]  (k-major, 8 nodes contiguous)

    const int o = threadIdx.x;
    for (int i = o; i < C1*C2; i += 256) sW[i] = W1a[i];
    const float bo = b1[o];
    __syncthreads();

    for (int d = blockIdx.x*8; d < N_NODES; d += gridDim.x*8) {
        for (int i = o; i < C1*8; i += 256) {
            const int k  = i & 127;
            const int nn = i >> 7;
            sX[k*8 + nn] = (d + nn < N_NODES) ? g_x1[(d+nn)*C1 + k] : 0.0f;
        }
        __syncthreads();

        unsigned long long a01 = pack2(bo, bo);
        unsigned long long a23 = pack2(bo, bo);
        unsigned long long a45 = pack2(bo, bo);
        unsigned long long a67 = pack2(bo, bo);
        #pragma unroll 4
        for (int k = 0; k < C1; k++) {
            const float w = sW[k*C2 + o];
            const unsigned long long ww = pack2(w, w);
            const ulonglong2* xp = reinterpret_cast<const ulonglong2*>(sX + k*8);
            const ulonglong2 x03 = xp[0];
            const ulonglong2 x47 = xp[1];
            ffma2(a01, x03.x, ww);
            ffma2(a23, x03.y, ww);
            ffma2(a45, x47.x, ww);
            ffma2(a67, x47.y, ww);
        }
        const float2 f01 = unpack2(a01);
        const float2 f23 = unpack2(a23);
        const float2 f45 = unpack2(a45);
        const float2 f67 = unpack2(a67);
        float r[8] = {f01.x,f01.y,f23.x,f23.y,f45.x,f45.y,f67.x,f67.y};
        #pragma unroll
        for (int nn = 0; nn < 8; nn++)
            if (d + nn < N_NODES) g_P[(d+nn)*C2 + o] = r[nn];
        __syncthreads();
    }
}

// =============================================================================
// Kernel 3: conv2 fused, 2 passes x 128 channels, 2 nodes per iteration.
// Phase C: each thread = (node, 2 channels, 8 edges): per k
//   1 LDS.64(w-pair) + 2 pack + 2 LDS.128(h) + 8 FFMA2  -> fma-pipe bound.
// Pipelined: next pair's esrc prefetched at top of B, pos loads under C.
// =============================================================================
#define K3_SW2   0
#define K3_SH    (C2*C1)                 // 32768
#define K3_SRED  (K3_SH + 2*C2*20)       // + 10240
#define K3_SREL  (K3_SRED + 512)
#define K3_SSRC  (K3_SREL + 2*DEG*4)
#define K3_SMEMF (K3_SSRC + 2*DEG)

__global__ __launch_bounds__(256, 1)
void k_conv2(const float* __restrict__ pos, const int* __restrict__ esrc,
             const float* __restrict__ W1full, const float* __restrict__ W2,
             const float* __restrict__ b2)
{
    extern __shared__ float sm[];
    float* sW2  = sm + K3_SW2;   // [256][128]  this pass's half of W2
    float* sH   = sm + K3_SH;    // [2][256][20]
    float* sRed = sm + K3_SRED;  // [256][2]
    float* sRel = sm + K3_SREL;  // [2][16][4]
    int*   sSrc = reinterpret_cast<int*>(sm + K3_SSRC);  // [2][16]

    const int tid  = threadIdx.x;
    const int pass = blockIdx.x & 1;
    const int nb   = blockIdx.x >> 1;
    const int STRIDE2 = (gridDim.x >> 1) * 2;
    const int base = nb * 2;

    for (int i = tid; i < C2*C1; i += 256) {
        const int k  = i >> 7;
        const int cc = i & 127;
        sW2[i] = W2[k*C2 + pass*C1 + cc];
    }
    const float w1b0 = W1full[(C1+0)*C2 + tid];
    const float w1b1 = W1full[(C1+1)*C2 + tid];
    const float w1b2 = W1full[(C1+2)*C2 + tid];

    const int node_sub = tid >> 7;          // 0..1
    const int jh       = (tid >> 6) & 1;    // edge half
    const int cp       = tid & 63;          // channel pair
    const float b2c    = b2[pass*C1 + (tid & 127)];

    // ---- prologue: src/rel for first pair ----
    if (tid < 2*DEG) {
        const int e = tid;
        const int s = esrc[base*DEG + e];
        const int dnode = base + (e >> 4);
        sSrc[e] = s;
        sRel[e*4+0] = pos[s*3+0] - pos[dnode*3+0];
        sRel[e*4+1] = pos[s*3+1] - pos[dnode*3+1];
        sRel[e*4+2] = pos[s*3+2] - pos[dnode*3+2];
    }
    __syncthreads();

    for (int d = base; d < N_NODES; d += STRIDE2) {
        const int dn = d + STRIDE2;
        const bool hn = (dn < N_NODES);
        // prefetch next pair's edge ids (latency hidden under phase B loads)
        int rSrcN = 0;
        if (tid < 2*DEG && hn) rSrcN = esrc[dn*DEG + tid];

        // ---- phase B: h1[nn][k=tid][j] = relu(P[src][tid] + rel@W1b) ----
        #pragma unroll
        for (int nn = 0; nn < 2; nn++) {
            int sj[DEG];
            #pragma unroll
            for (int j = 0; j < DEG; j++) sj[j] = sSrc[nn*DEG + j];
            float v[DEG];
            #pragma unroll
            for (int j = 0; j < DEG; j++) v[j] = g_P[sj[j]*C2 + tid];
            #pragma unroll
            for (int j = 0; j < DEG; j++) {
                float t = v[j];
                t = fmaf(sRel[(nn*DEG+j)*4+0], w1b0, t);
                t = fmaf(sRel[(nn*DEG+j)*4+1], w1b1, t);
                t = fmaf(sRel[(nn*DEG+j)*4+2], w1b2, t);
                sH[nn*(C2*20) + tid*20 + j] = fmaxf(t, 0.0f);
            }
        }
        __syncthreads();   // (1) sH ready, sSrc/sRel free

        // issue pos loads for next pair (esrc arrived during B); hidden under C
        float psx=0.f, psy=0.f, psz=0.f, pdx=0.f, pdy=0.f, pdz=0.f;
        if (tid < 2*DEG && hn) {
            psx = pos[rSrcN*3+0]; psy = pos[rSrcN*3+1]; psz = pos[rSrcN*3+2];
            const int dnode = dn + (tid >> 4);
            pdx = pos[dnode*3+0]; pdy = pos[dnode*3+1]; pdz = pos[dnode*3+2];
        }

        // ---- phase C: per-thread 2 channels x 8 edges over k=0..255 ----
        unsigned long long aA0=0ull,aA1=0ull,aA2=0ull,aA3=0ull;
        unsigned long long aB0=0ull,aB1=0ull,aB2=0ull,aB3=0ull;
        const float* hbase = sH + node_sub*(C2*20) + jh*8;
        const float* wbase = sW2 + 2*cp;
        #pragma unroll 4
        for (int k = 0; k < C2; k++) {
            const float2 wv = *reinterpret_cast<const float2*>(wbase + k*C1);
            const unsigned long long w0 = pack2(wv.x, wv.x);
            const unsigned long long w1 = pack2(wv.y, wv.y);
            const ulonglong2* hp = reinterpret_cast<const ulonglong2*>(hbase + k*20);
            const ulonglong2 ha = hp[0];
            const ulonglong2 hb = hp[1];
            ffma2(aA0, ha.x, w0); ffma2(aA1, ha.y, w0);
            ffma2(aA2, hb.x, w0); ffma2(aA3, hb.y, w0);
            ffma2(aB0, ha.x, w1); ffma2(aB1, ha.y, w1);
            ffma2(aB2, hb.x, w1); ffma2(aB3, hb.y, w1);
        }
        float m0 = -3.4e38f, m1 = -3.4e38f;
        {
            float2 f;
            f = unpack2(aA0); m0 = fmaxf(m0, fmaxf(f.x, f.y));
            f = unpack2(aA1); m0 = fmaxf(m0, fmaxf(f.x, f.y));
            f = unpack2(aA2); m0 = fmaxf(m0, fmaxf(f.x, f.y));
            f = unpack2(aA3); m0 = fmaxf(m0, fmaxf(f.x, f.y));
            f = unpack2(aB0); m1 = fmaxf(m1, fmaxf(f.x, f.y));
            f = unpack2(aB1); m1 = fmaxf(m1, fmaxf(f.x, f.y));
            f = unpack2(aB2); m1 = fmaxf(m1, fmaxf(f.x, f.y));
            f = unpack2(aB3); m1 = fmaxf(m1, fmaxf(f.x, f.y));
        }
        sRed[tid*2 + 0] = m0;
        sRed[tid*2 + 1] = m1;
        __syncthreads();   // (2) partials ready

        {   // combine jh halves; thread t -> (node t>>7, channel t&127)
            const int n  = tid >> 7;
            const int ch = tid & 127;
            const int cq = ch >> 1;
            const int lo = ch & 1;
            const float v = fmaxf(sRed[(n*128 + cq)*2 + lo],
                                  sRed[(n*128 + 64 + cq)*2 + lo]);
            g_x2[(d + n)*C2 + pass*C1 + ch] = v + b2c;
        }
        // store next pair's src/rel from prefetched values
        if (tid < 2*DEG && hn) {
            sSrc[tid] = rSrcN;
            sRel[tid*4+0] = psx - pdx;
            sRel[tid*4+1] = psy - pdy;
            sRel[tid*4+2] = psz - pdz;
        }
        __syncthreads();   // (3) gate next B
    }
}

// =============================================================================
// Kernel 4a: partial global-max pool. grid = 16 graphs * 80 chunks (MLP).
// =============================================================================
__global__ void k_pool_partial()
{
    const int g    = blockIdx.x / PCH;
    const int ch   = blockIdx.x % PCH;
    const int cidx = threadIdx.x;
    const int s = (ch     * NPG) / PCH;
    const int e = ((ch+1) * NPG) / PCH;
    float m = -3.4e38f;
    #pragma unroll 4
    for (int n = s; n < e; n++)
        m = fmaxf(m, g_x2[(g*NPG + n)*C2 + cidx]);
    g_part[(g*PCH + ch)*C2 + cidx] = m;
}

// =============================================================================
// Kernel 4b: final pool + FC head. 16 blocks (one per graph), 256 threads.
// =============================================================================
__global__ __launch_bounds__(256)
void k_head(const float* __restrict__ fc1W, const float* __restrict__ fc1b,
            const float* __restrict__ fc2W, const float* __restrict__ fc2b,
            const float* __restrict__ labW, const float* __restrict__ labb,
            const float* __restrict__ boxW, const float* __restrict__ boxb,
            float* __restrict__ out)
{
    __shared__ float sp[C2];
    __shared__ float sy1[C2];
    __shared__ float sy2[C1];
    const int g = blockIdx.x;
    const int t = threadIdx.x;

    float m = -3.4e38f;
    #pragma unroll 8
    for (int ch = 0; ch < PCH; ch++)
        m = fmaxf(m, g_part[(g*PCH + ch)*C2 + t]);
    sp[t] = m;
    __syncthreads();

    float a = fc1b[t];
    #pragma unroll 8
    for (int k = 0; k < C2; k++) a = fmaf(sp[k], fc1W[k*C2 + t], a);
    sy1[t] = fmaxf(a, 0.0f);
    __syncthreads();

    if (t < C1) {
        float b = fc2b[t];
        #pragma unroll 8
        for (int k = 0; k < C2; k++) b = fmaf(sy1[k], fc2W[k*C1 + t], b);
        sy2[t] = fmaxf(b, 0.0f);
    }
    __syncthreads();

    if (t < 10) {
        float a2 = labb[t];
        #pragma unroll 8
        for (int k = 0; k < C1; k++) a2 = fmaf(sy2[k], labW[k*10 + t], a2);
        out[g*10 + t] = a2;                       // labels [16,10]
    } else if (t >= 32 && t < 38) {
        const int bt = t - 32;
        float a2 = boxb[bt];
        #pragma unroll 8
        for (int k = 0; k < C1; k++) a2 = fmaf(sy2[k], boxW[k*6 + bt], a2);
        out[NGR*10 + g*6 + bt] = a2;              // bbox [16,6] after labels
    }
}

// =============================================================================
extern "C" void kernel_launch(void* const* d_in, const int* in_sizes, int n_in,
                              void* d_out, int out_size)
{
    const float* pos  = (const float*)d_in[0];
    const int*   esrc = (const int*)  d_in[1];
    // d_in[2] edge_dst = repeat(arange(N),16), d_in[3] batch = n/1250 (structural)
    const float* c1W1 = (const float*)d_in[4];
    const float* c1b1 = (const float*)d_in[5];
    const float* c1W2 = (const float*)d_in[6];
    const float* c1b2 = (const float*)d_in[7];
    const float* c2W1 = (const float*)d_in[8];
    const float* c2b1 = (const float*)d_in[9];
    const float* c2W2 = (const float*)d_in[10];
    const float* c2b2 = (const float*)d_in[11];
    const float* fc1W = (const float*)d_in[12];
    const float* fc1b = (const float*)d_in[13];
    const float* fc2W = (const float*)d_in[14];
    const float* fc2b = (const float*)d_in[15];
    const float* labW = (const float*)d_in[16];
    const float* labb = (const float*)d_in[17];
    const float* boxW = (const float*)d_in[18];
    const float* boxb = (const float*)d_in[19];
    float* out = (float*)d_out;

    cudaFuncSetAttribute(k_conv1, cudaFuncAttributeMaxDynamicSharedMemorySize, K1_SMEMF*4);
    cudaFuncSetAttribute(k_proj,  cudaFuncAttributeMaxDynamicSharedMemorySize, K2_SMEMF*4);
    cudaFuncSetAttribute(k_conv2, cudaFuncAttributeMaxDynamicSharedMemorySize, K3_SMEMF*4);

    k_conv1<<<296, 128, K1_SMEMF*4>>>(pos, esrc, c1W1, c1b1, c1W2, c1b2);
    k_proj <<<148, 256, K2_SMEMF*4>>>(c2W1, c2b1);
    k_conv2<<<296, 256, K3_SMEMF*4>>>(pos, esrc, c2W1, c2W2, c2b2);
    k_pool_partial<<<NGR*PCH, 256>>>();
    k_head<<<NGR, 256>>>(fc1W, fc1b, fc2W, fc2b, labW, labb, boxW, boxb, out);
}

// round 12
// speedup vs baseline: 1.4552x; 1.0016x over previous
#include <cuda_runtime.h>

#define N_NODES 20000
#define DEG     16
#define C1      128
#define C2      256
#define NGR     16
#define NPG     1250   // nodes per graph (20000/16)
#define PCH     80     // pool chunks per graph

// ---------------- scratch (device globals; no allocation allowed) -------------
__device__ float g_x1[N_NODES * C1];        // conv1 output       [N,128]
__device__ float g_P [N_NODES * C2];        // x1 @ c2_W1a + b1   [N,256]  (L2-resident, 20MB)
__device__ float g_x2[N_NODES * C2];        // conv2 output       [N,256]
__device__ float g_part[NGR * PCH * C2];    // partial graph-max pool

// ---------------- f32x2 packed-FMA helpers (Blackwell, PTX-only) --------------
__device__ __forceinline__ unsigned long long pack2(float lo, float hi) {
    unsigned long long r;
    asm("mov.b64 %0, {%1, %2};" : "=l"(r) : "f"(lo), "f"(hi));
    return r;
}
__device__ __forceinline__ void ffma2(unsigned long long &acc,
                                      unsigned long long a,
                                      unsigned long long b) {
    asm("fma.rn.f32x2 %0, %1, %2, %0;" : "+l"(acc) : "l"(a), "l"(b));
}
__device__ __forceinline__ float2 unpack2(unsigned long long v) {
    float lo, hi;
    asm("mov.b64 {%0, %1}, %2;" : "=f"(lo), "=f"(hi) : "l"(v));
    return make_float2(lo, hi);
}

// =============================================================================
// Kernel 1: conv1 fused, depth-2 pipelined edge gather.
// Per node: msg[16,6] -> relu(@W1+b1) -> h1[16,128] (smem, transposed) -> @W2
// -> max over 16 -> x1[d,128]+b2.  128 threads = 128 channels, 2 blocks/SM.
// =============================================================================
#define K1_SW2   0
#define K1_SH    (C1*C1)                 // 16384
#define K1_SMSG  (K1_SH + C1*20)         // + 2560
#define K1_SMEMF (K1_SMSG + DEG*8)       // + 128

__global__ __launch_bounds__(128, 2)
void k_conv1(const float* __restrict__ pos, const int* __restrict__ esrc,
             const float* __restrict__ W1, const float* __restrict__ b1,
             const float* __restrict__ W2, const float* __restrict__ b2)
{
    extern __shared__ float sm[];
    float* sW2  = sm + K1_SW2;    // [128][128]  (k-major, c contiguous)
    float* sH   = sm + K1_SH;     // [128][20]   h1 transposed
    float* sMsg = sm + K1_SMSG;   // [16][8]

    const int c = threadIdx.x;
    const int S = gridDim.x;
    const int base = blockIdx.x;

    for (int i = c; i < C1*C1; i += 128) sW2[i] = W2[i];

    float w1r[6];
    #pragma unroll
    for (int i = 0; i < 6; i++) w1r[i] = W1[i*C1 + c];
    const float b1c = b1[c];
    const float b2c = b2[c];

    // ---- prologue: msg(base) direct, prefetch esrc(base+S) ----
    if (c < DEG) {
        const int s = esrc[base*DEG + c];
        const float pdx = pos[base*3+0], pdy = pos[base*3+1], pdz = pos[base*3+2];
        const float psx = pos[s*3+0], psy = pos[s*3+1], psz = pos[s*3+2];
        float* m = sMsg + c*8;
        m[0]=psx; m[1]=psy; m[2]=psz;
        m[3]=psx-pdx; m[4]=psy-pdy; m[5]=psz-pdz;
    }
    int rSrcA = 0;
    if (c < DEG && base + S < N_NODES) rSrcA = esrc[(base+S)*DEG + c];
    __syncthreads();

    for (int d = base; d < N_NODES; d += S) {
        // ---- phase B: h1[j][c] = relu(msg@W1 + b1) ----
        #pragma unroll
        for (int j = 0; j < DEG; j++) {
            const float* m = sMsg + j*8;
            float h = b1c;
            #pragma unroll
            for (int i = 0; i < 6; i++) h = fmaf(m[i], w1r[i], h);
            sH[c*20 + j] = fmaxf(h, 0.0f);
        }
        // prefetch esrc for d+2S (depth-2)
        int rSrcB = 0;
        const int d2 = d + 2*S;
        if (c < DEG && d2 < N_NODES) rSrcB = esrc[d2*DEG + c];
        __syncthreads();   // (1) sH ready, sMsg free

        // issue pos loads for next node (esrc already arrived); hidden under C
        const int dn = d + S;
        const bool hn = (dn < N_NODES);
        float psx=0.f, psy=0.f, psz=0.f, pdx=0.f, pdy=0.f, pdz=0.f;
        if (c < DEG && hn) {
            psx = pos[rSrcA*3+0]; psy = pos[rSrcA*3+1]; psz = pos[rSrcA*3+2];
            pdx = pos[dn*3+0];    pdy = pos[dn*3+1];    pdz = pos[dn*3+2];
        }

        // ---- phase C: out[c] = max_j (h1[j,:] @ W2[:,c]) + b2[c] ----
        unsigned long long a0=0ull,a1=0ull,a2=0ull,a3=0ull,a4=0ull,a5=0ull,a6=0ull,a7=0ull;
        #pragma unroll 4
        for (int k = 0; k < C1; k++) {
            const float w = sW2[k*C1 + c];
            const unsigned long long ww = pack2(w, w);
            const ulonglong2* hp = reinterpret_cast<const ulonglong2*>(sH + k*20);
            const ulonglong2 h0 = hp[0];
            const ulonglong2 h1v = hp[1];
            const ulonglong2 h2 = hp[2];
            const ulonglong2 h3 = hp[3];
            ffma2(a0, h0.x, ww);  ffma2(a1, h0.y, ww);
            ffma2(a2, h1v.x, ww); ffma2(a3, h1v.y, ww);
            ffma2(a4, h2.x, ww);  ffma2(a5, h2.y, ww);
            ffma2(a6, h3.x, ww);  ffma2(a7, h3.y, ww);
        }
        float m = -3.4e38f;
        {
            float2 f;
            f = unpack2(a0); m = fmaxf(m, fmaxf(f.x, f.y));
            f = unpack2(a1); m = fmaxf(m, fmaxf(f.x, f.y));
            f = unpack2(a2); m = fmaxf(m, fmaxf(f.x, f.y));
            f = unpack2(a3); m = fmaxf(m, fmaxf(f.x, f.y));
            f = unpack2(a4); m = fmaxf(m, fmaxf(f.x, f.y));
            f = unpack2(a5); m = fmaxf(m, fmaxf(f.x, f.y));
            f = unpack2(a6); m = fmaxf(m, fmaxf(f.x, f.y));
            f = unpack2(a7); m = fmaxf(m, fmaxf(f.x, f.y));
        }
        g_x1[d*C1 + c] = m + b2c;

        // store msg(d+S) from prefetched pos
        if (c < DEG && hn) {
            float* mm = sMsg + c*8;
            mm[0]=psx; mm[1]=psy; mm[2]=psz;
            mm[3]=psx-pdx; mm[4]=psy-pdy; mm[5]=psz-pdz;
        }
        rSrcA = rSrcB;
        __syncthreads();   // (2) sMsg ready for next B
    }
}

// =============================================================================
// Kernel 2: P[n,o] = b1[o] + x1[n,:] @ c2_W1[0:128,o].  W1a (128KB) in smem.
// 8 nodes per iteration; f32x2 pairs across nodes -> 8 issue / 8 fma per k.
// =============================================================================
#define K2_SW    0
#define K2_SX    (C1*C2)            // 32768
#define K2_SMEMF (K2_SX + C1*8)

__global__ __launch_bounds__(256, 1)
void k_proj(const float* __restrict__ W1a, const float* __restrict__ b1)
{
    extern __shared__ float sm[];
    float* sW = sm + K2_SW;     // [128][256]
    float* sX = sm + K2_SX;     // [128][8]  (k-major, 8 nodes contiguous)

    const int o = threadIdx.x;
    for (int i = o; i < C1*C2; i += 256) sW[i] = W1a[i];
    const float bo = b1[o];
    __syncthreads();

    for (int d = blockIdx.x*8; d < N_NODES; d += gridDim.x*8) {
        for (int i = o; i < C1*8; i += 256) {
            const int k  = i & 127;
            const int nn = i >> 7;
            sX[k*8 + nn] = (d + nn < N_NODES) ? g_x1[(d+nn)*C1 + k] : 0.0f;
        }
        __syncthreads();

        unsigned long long a01 = pack2(bo, bo);
        unsigned long long a23 = pack2(bo, bo);
        unsigned long long a45 = pack2(bo, bo);
        unsigned long long a67 = pack2(bo, bo);
        #pragma unroll 4
        for (int k = 0; k < C1; k++) {
            const float w = sW[k*C2 + o];
            const unsigned long long ww = pack2(w, w);
            const ulonglong2* xp = reinterpret_cast<const ulonglong2*>(sX + k*8);
            const ulonglong2 x03 = xp[0];
            const ulonglong2 x47 = xp[1];
            ffma2(a01, x03.x, ww);
            ffma2(a23, x03.y, ww);
            ffma2(a45, x47.x, ww);
            ffma2(a67, x47.y, ww);
        }
        const float2 f01 = unpack2(a01);
        const float2 f23 = unpack2(a23);
        const float2 f45 = unpack2(a45);
        const float2 f67 = unpack2(a67);
        float r[8] = {f01.x,f01.y,f23.x,f23.y,f45.x,f45.y,f67.x,f67.y};
        #pragma unroll
        for (int nn = 0; nn < 8; nn++)
            if (d + nn < N_NODES) g_P[(d+nn)*C2 + o] = r[nn];
        __syncthreads();
    }
}

// =============================================================================
// Kernel 3: conv2 fused, 2 passes x 128 channels, 2 nodes per iteration.
// Phase C: each thread = (node, 2 channels, 8 edges): per k
//   1 LDS.64(w-pair) + 2 pack + 2 LDS.128(h) + 8 FFMA2  -> fma-pipe bound.
// Pipelined: next pair's esrc prefetched at top of B, pos loads under C.
// =============================================================================
#define K3_SW2   0
#define K3_SH    (C2*C1)                 // 32768
#define K3_SRED  (K3_SH + 2*C2*20)       // + 10240
#define K3_SREL  (K3_SRED + 512)
#define K3_SSRC  (K3_SREL + 2*DEG*4)
#define K3_SMEMF (K3_SSRC + 2*DEG)

__global__ __launch_bounds__(256, 1)
void k_conv2(const float* __restrict__ pos, const int* __restrict__ esrc,
             const float* __restrict__ W1full, const float* __restrict__ W2,
             const float* __restrict__ b2)
{
    extern __shared__ float sm[];
    float* sW2  = sm + K3_SW2;   // [256][128]  this pass's half of W2
    float* sH   = sm + K3_SH;    // [2][256][20]
    float* sRed = sm + K3_SRED;  // [256][2]
    float* sRel = sm + K3_SREL;  // [2][16][4]
    int*   sSrc = reinterpret_cast<int*>(sm + K3_SSRC);  // [2][16]

    const int tid  = threadIdx.x;
    const int pass = blockIdx.x & 1;
    const int nb   = blockIdx.x >> 1;
    const int STRIDE2 = (gridDim.x >> 1) * 2;
    const int base = nb * 2;

    for (int i = tid; i < C2*C1; i += 256) {
        const int k  = i >> 7;
        const int cc = i & 127;
        sW2[i] = W2[k*C2 + pass*C1 + cc];
    }
    const float w1b0 = W1full[(C1+0)*C2 + tid];
    const float w1b1 = W1full[(C1+1)*C2 + tid];
    const float w1b2 = W1full[(C1+2)*C2 + tid];

    const int node_sub = tid >> 7;          // 0..1
    const int jh       = (tid >> 6) & 1;    // edge half
    const int cp       = tid & 63;          // channel pair
    const float b2c    = b2[pass*C1 + (tid & 127)];

    // ---- prologue: src/rel for first pair ----
    if (tid < 2*DEG) {
        const int e = tid;
        const int s = esrc[base*DEG + e];
        const int dnode = base + (e >> 4);
        sSrc[e] = s;
        sRel[e*4+0] = pos[s*3+0] - pos[dnode*3+0];
        sRel[e*4+1] = pos[s*3+1] - pos[dnode*3+1];
        sRel[e*4+2] = pos[s*3+2] - pos[dnode*3+2];
    }
    __syncthreads();

    for (int d = base; d < N_NODES; d += STRIDE2) {
        const int dn = d + STRIDE2;
        const bool hn = (dn < N_NODES);
        // prefetch next pair's edge ids (latency hidden under phase B loads)
        int rSrcN = 0;
        if (tid < 2*DEG && hn) rSrcN = esrc[dn*DEG + tid];

        // ---- phase B: h1[nn][k=tid][j] = relu(P[src][tid] + rel@W1b) ----
        #pragma unroll
        for (int nn = 0; nn < 2; nn++) {
            int sj[DEG];
            #pragma unroll
            for (int j = 0; j < DEG; j++) sj[j] = sSrc[nn*DEG + j];
            float v[DEG];
            #pragma unroll
            for (int j = 0; j < DEG; j++) v[j] = g_P[sj[j]*C2 + tid];
            #pragma unroll
            for (int j = 0; j < DEG; j++) {
                float t = v[j];
                t = fmaf(sRel[(nn*DEG+j)*4+0], w1b0, t);
                t = fmaf(sRel[(nn*DEG+j)*4+1], w1b1, t);
                t = fmaf(sRel[(nn*DEG+j)*4+2], w1b2, t);
                sH[nn*(C2*20) + tid*20 + j] = fmaxf(t, 0.0f);
            }
        }
        __syncthreads();   // (1) sH ready, sSrc/sRel free

        // issue pos loads for next pair (esrc arrived during B); hidden under C
        float psx=0.f, psy=0.f, psz=0.f, pdx=0.f, pdy=0.f, pdz=0.f;
        if (tid < 2*DEG && hn) {
            psx = pos[rSrcN*3+0]; psy = pos[rSrcN*3+1]; psz = pos[rSrcN*3+2];
            const int dnode = dn + (tid >> 4);
            pdx = pos[dnode*3+0]; pdy = pos[dnode*3+1]; pdz = pos[dnode*3+2];
        }

        // ---- phase C: per-thread 2 channels x 8 edges over k=0..255 ----
        unsigned long long aA0=0ull,aA1=0ull,aA2=0ull,aA3=0ull;
        unsigned long long aB0=0ull,aB1=0ull,aB2=0ull,aB3=0ull;
        const float* hbase = sH + node_sub*(C2*20) + jh*8;
        const float* wbase = sW2 + 2*cp;
        #pragma unroll 4
        for (int k = 0; k < C2; k++) {
            const float2 wv = *reinterpret_cast<const float2*>(wbase + k*C1);
            const unsigned long long w0 = pack2(wv.x, wv.x);
            const unsigned long long w1 = pack2(wv.y, wv.y);
            const ulonglong2* hp = reinterpret_cast<const ulonglong2*>(hbase + k*20);
            const ulonglong2 ha = hp[0];
            const ulonglong2 hb = hp[1];
            ffma2(aA0, ha.x, w0); ffma2(aA1, ha.y, w0);
            ffma2(aA2, hb.x, w0); ffma2(aA3, hb.y, w0);
            ffma2(aB0, ha.x, w1); ffma2(aB1, ha.y, w1);
            ffma2(aB2, hb.x, w1); ffma2(aB3, hb.y, w1);
        }
        float m0 = -3.4e38f, m1 = -3.4e38f;
        {
            float2 f;
            f = unpack2(aA0); m0 = fmaxf(m0, fmaxf(f.x, f.y));
            f = unpack2(aA1); m0 = fmaxf(m0, fmaxf(f.x, f.y));
            f = unpack2(aA2); m0 = fmaxf(m0, fmaxf(f.x, f.y));
            f = unpack2(aA3); m0 = fmaxf(m0, fmaxf(f.x, f.y));
            f = unpack2(aB0); m1 = fmaxf(m1, fmaxf(f.x, f.y));
            f = unpack2(aB1); m1 = fmaxf(m1, fmaxf(f.x, f.y));
            f = unpack2(aB2); m1 = fmaxf(m1, fmaxf(f.x, f.y));
            f = unpack2(aB3); m1 = fmaxf(m1, fmaxf(f.x, f.y));
        }
        sRed[tid*2 + 0] = m0;
        sRed[tid*2 + 1] = m1;
        __syncthreads();   // (2) partials ready

        {   // combine jh halves; thread t -> (node t>>7, channel t&127)
            const int n  = tid >> 7;
            const int ch = tid & 127;
            const int cq = ch >> 1;
            const int lo = ch & 1;
            const float v = fmaxf(sRed[(n*128 + cq)*2 + lo],
                                  sRed[(n*128 + 64 + cq)*2 + lo]);
            g_x2[(d + n)*C2 + pass*C1 + ch] = v + b2c;
        }
        // store next pair's src/rel from prefetched values
        if (tid < 2*DEG && hn) {
            sSrc[tid] = rSrcN;
            sRel[tid*4+0] = psx - pdx;
            sRel[tid*4+1] = psy - pdy;
            sRel[tid*4+2] = psz - pdz;
        }
        __syncthreads();   // (3) gate next B
    }
}

// =============================================================================
// Kernel 4a: partial global-max pool. grid = 16 graphs * 80 chunks (MLP).
// =============================================================================
__global__ void k_pool_partial()
{
    const int g    = blockIdx.x / PCH;
    const int ch   = blockIdx.x % PCH;
    const int cidx = threadIdx.x;
    const int s = (ch     * NPG) / PCH;
    const int e = ((ch+1) * NPG) / PCH;
    float m = -3.4e38f;
    #pragma unroll 4
    for (int n = s; n < e; n++)
        m = fmaxf(m, g_x2[(g*NPG + n)*C2 + cidx]);
    g_part[(g*PCH + ch)*C2 + cidx] = m;
}

// =============================================================================
// Kernel 4b: final pool + FC head. 16 blocks (one per graph), 256 threads.
// =============================================================================
__global__ __launch_bounds__(256)
void k_head(const float* __restrict__ fc1W, const float* __restrict__ fc1b,
            const float* __restrict__ fc2W, const float* __restrict__ fc2b,
            const float* __restrict__ labW, const float* __restrict__ labb,
            const float* __restrict__ boxW, const float* __restrict__ boxb,
            float* __restrict__ out)
{
    __shared__ float sp[C2];
    __shared__ float sy1[C2];
    __shared__ float sy2[C1];
    const int g = blockIdx.x;
    const int t = threadIdx.x;

    float m = -3.4e38f;
    #pragma unroll 8
    for (int ch = 0; ch < PCH; ch++)
        m = fmaxf(m, g_part[(g*PCH + ch)*C2 + t]);
    sp[t] = m;
    __syncthreads();

    float a = fc1b[t];
    #pragma unroll 8
    for (int k = 0; k < C2; k++) a = fmaf(sp[k], fc1W[k*C2 + t], a);
    sy1[t] = fmaxf(a, 0.0f);
    __syncthreads();

    if (t < C1) {
        float b = fc2b[t];
        #pragma unroll 8
        for (int k = 0; k < C2; k++) b = fmaf(sy1[k], fc2W[k*C1 + t], b);
        sy2[t] = fmaxf(b, 0.0f);
    }
    __syncthreads();

    if (t < 10) {
        float a2 = labb[t];
        #pragma unroll 8
        for (int k = 0; k < C1; k++) a2 = fmaf(sy2[k], labW[k*10 + t], a2);
        out[g*10 + t] = a2;                       // labels [16,10]
    } else if (t >= 32 && t < 38) {
        const int bt = t - 32;
        float a2 = boxb[bt];
        #pragma unroll 8
        for (int k = 0; k < C1; k++) a2 = fmaf(sy2[k], boxW[k*6 + bt], a2);
        out[NGR*10 + g*6 + bt] = a2;              // bbox [16,6] after labels
    }
}

// =============================================================================
extern "C" void kernel_launch(void* const* d_in, const int* in_sizes, int n_in,
                              void* d_out, int out_size)
{
    const float* pos  = (const float*)d_in[0];
    const int*   esrc = (const int*)  d_in[1];
    // d_in[2] edge_dst = repeat(arange(N),16), d_in[3] batch = n/1250 (structural)
    const float* c1W1 = (const float*)d_in[4];
    const float* c1b1 = (const float*)d_in[5];
    const float* c1W2 = (const float*)d_in[6];
    const float* c1b2 = (const float*)d_in[7];
    const float* c2W1 = (const float*)d_in[8];
    const float* c2b1 = (const float*)d_in[9];
    const float* c2W2 = (const float*)d_in[10];
    const float* c2b2 = (const float*)d_in[11];
    const float* fc1W = (const float*)d_in[12];
    const float* fc1b = (const float*)d_in[13];
    const float* fc2W = (const float*)d_in[14];
    const float* fc2b = (const float*)d_in[15];
    const float* labW = (const float*)d_in[16];
    const float* labb = (const float*)d_in[17];
    const float* boxW = (const float*)d_in[18];
    const float* boxb = (const float*)d_in[19];
    float* out = (float*)d_out;

    cudaFuncSetAttribute(k_conv1, cudaFuncAttributeMaxDynamicSharedMemorySize, K1_SMEMF*4);
    cudaFuncSetAttribute(k_proj,  cudaFuncAttributeMaxDynamicSharedMemorySize, K2_SMEMF*4);
    cudaFuncSetAttribute(k_conv2, cudaFuncAttributeMaxDynamicSharedMemorySize, K3_SMEMF*4);

    k_conv1<<<296, 128, K1_SMEMF*4>>>(pos, esrc, c1W1, c1b1, c1W2, c1b2);
    k_proj <<<148, 256, K2_SMEMF*4>>>(c2W1, c2b1);
    k_conv2<<<296, 256, K3_SMEMF*4>>>(pos, esrc, c2W1, c2W2, c2b2);
    k_pool_partial<<<NGR*PCH, 256>>>();
    k_head<<<NGR, 256>>>(fc1W, fc1b, fc2W, fc2b, labW, labb, boxW, boxb, out);
}